// round 14
// baseline (speedup 1.0000x reference)
#include <cuda_runtime.h>
#include <cuda_bf16.h>
#include <math.h>
#include <stdint.h>

#define NB 16
#define NTE 64
#define NTD 32
#define NE 256
#define NH 512
#define NG 2048
#define NV 90000
#define NEGV (-1e9f)
#define KE 768
#define PAE (KE + 8)
#define KD 1280
#define PAD (KD + 8)

typedef unsigned long long u64;

// ---------------- device scratch ----------------
__device__ float g_qemb[NB*NTE*NE];
__device__ float g_remb[NB*NTD*NE];
__device__ float g_h[2][NB*NH];
__device__ float g_c[2][NB*NH];
__device__ float g_attn[NB*NH];
__device__ float g_encout[NB*NTE*NH];
__device__ float g_keys[NB*NTE*NH];
__device__ float g_pq[NB*NH];
__device__ float g_ctx[NB*NH];
__device__ int   g_outrow[NB*NTD];
__device__ int   g_rowpos[NB*NTD];
__device__ int   g_nrows;
// bf16 hi/lo LSTM weights, per-CTA n-permuted: Wz[(c*16+gl)][k]
__device__ __nv_bfloat16 g_Wze_hi[(size_t)NG*KE];
__device__ __nv_bfloat16 g_Wze_lo[(size_t)NG*KE];
__device__ __nv_bfloat16 g_Wzd_hi[(size_t)NG*KD];
__device__ __nv_bfloat16 g_Wzd_lo[(size_t)NG*KD];
__device__ float g_Wq2[128*512*4];     // [c][k][j]
__device__ float g_Wa2[128*1024*4];    // [c][k][j]
__device__ __nv_bfloat16 g_Ahi[512*NH];
__device__ __nv_bfloat16 g_Alo[512*NH];

// ---------------- fast math ----------------
__device__ __forceinline__ float fsig(float x) {
    return __fdividef(1.f, 1.f + __expf(-x));
}
__device__ __forceinline__ float ftanh(float x) {
    x = fminf(fmaxf(x, -15.f), 15.f);
    float a = __expf(2.f * x);
    return __fdividef(a - 1.f, a + 1.f);
}
__device__ __forceinline__ uint32_t smem_u32(const void* p) {
    uint32_t a;
    asm("{ .reg .u64 t; cvta.to.shared.u64 t, %1; cvt.u32.u64 %0, t; }" : "=r"(a) : "l"(p));
    return a;
}

// ---------------- HMMA helpers (verified in proj since round 6) ----------------
__device__ __forceinline__ void ldmA(uint32_t* a, uint32_t addr) {
    asm volatile("ldmatrix.sync.aligned.m8n8.x4.shared.b16 {%0,%1,%2,%3}, [%4];"
                 : "=r"(a[0]), "=r"(a[1]), "=r"(a[2]), "=r"(a[3]) : "r"(addr));
}
__device__ __forceinline__ void ldmB(uint32_t* b, uint32_t addr) {
    asm volatile("ldmatrix.sync.aligned.m8n8.x2.shared.b16 {%0,%1}, [%2];"
                 : "=r"(b[0]), "=r"(b[1]) : "r"(addr));
}
__device__ __forceinline__ void mma16816(float* c, const uint32_t* a, const uint32_t* b) {
    asm volatile("mma.sync.aligned.m16n8k16.row.col.f32.bf16.bf16.f32 "
                 "{%0,%1,%2,%3}, {%4,%5,%6,%7}, {%8,%9}, {%0,%1,%2,%3};"
                 : "+f"(c[0]), "+f"(c[1]), "+f"(c[2]), "+f"(c[3])
                 : "r"(a[0]), "r"(a[1]), "r"(a[2]), "r"(a[3]), "r"(b[0]), "r"(b[1]));
}

// ---------------- prep ----------------
__global__ void prep_kernel(const int* __restrict__ enc_in, const int* __restrict__ dec_in,
                            const int* __restrict__ dlen, const float* __restrict__ emb)
{
    int idx = blockIdx.x * blockDim.x + threadIdx.x;
    int stride = gridDim.x * blockDim.x;
    for (int i = idx; i < NB*NTE*NE; i += stride) {
        int e = i & (NE - 1); int bt = i >> 8;
        g_qemb[i] = emb[(size_t)enc_in[bt] * NE + e];
    }
    for (int i = idx; i < NB*NTD*NE; i += stride) {
        int e = i & (NE - 1); int bt = i >> 8;
        g_remb[i] = emb[(size_t)dec_in[bt] * NE + e];
    }
    for (int i = idx; i < NB*NH; i += stride) {
        g_h[0][i] = 0.f; g_c[0][i] = 0.f; g_attn[i] = 0.f;
    }
    __nv_bfloat16 z = __float2bfloat16(0.f);
    for (int i = idx; i < 512*NH; i += stride) { g_Ahi[i] = z; g_Alo[i] = z; }
    if (idx == 0) {
        int n = 0;
        for (int b = 0; b < NB; b++) {
            int L = dlen[b]; if (L > NTD) L = NTD; if (L < 0) L = 0;
            for (int t2 = 0; t2 < NTD; t2++) {
                if (t2 < L) { g_outrow[n] = b*NTD + t2; g_rowpos[b*NTD + t2] = n; n++; }
                else g_rowpos[b*NTD + t2] = -1;
            }
        }
        g_nrows = n;
    }
}

// ---------------- permute + split weights ----------------
// Wz[(c*16 + gl)*K + k] = W[k*2048 + q*512 + c*4 + jl],  gl = jl*4 + q, split bf16 hi/lo
__global__ void permW_kernel(const float* __restrict__ We, const float* __restrict__ Wd,
                             const float* __restrict__ Wq, const float* __restrict__ Wa)
{
    int idx = blockIdx.x * blockDim.x + threadIdx.x;
    int stride = gridDim.x * blockDim.x;
    for (int i = idx; i < NG*KE; i += stride) {
        int k = i % KE, n = i / KE;
        int gl = n & 15, c = n >> 4;
        int jl = gl >> 2, q = gl & 3;
        float v = We[(size_t)k*NG + q*NH + (c << 2) + jl];
        __nv_bfloat16 hi = __float2bfloat16(v);
        g_Wze_hi[i] = hi;
        g_Wze_lo[i] = __float2bfloat16(v - __bfloat162float(hi));
    }
    for (int i = idx; i < NG*KD; i += stride) {
        int k = i % KD, n = i / KD;
        int gl = n & 15, c = n >> 4;
        int jl = gl >> 2, q = gl & 3;
        float v = Wd[(size_t)k*NG + q*NH + (c << 2) + jl];
        __nv_bfloat16 hi = __float2bfloat16(v);
        g_Wzd_hi[i] = hi;
        g_Wzd_lo[i] = __float2bfloat16(v - __bfloat162float(hi));
    }
    for (int i = idx; i < 128*512*4; i += stride) {
        int j = i & 3, r = i >> 2;
        int k = r & 511, c = r >> 9;
        g_Wq2[i] = Wq[(size_t)k*NH + (c << 2) + j];
    }
    for (int i = idx; i < 128*1024*4; i += stride) {
        int j = i & 3, r = i >> 2;
        int k = r & 1023, c = r >> 10;
        g_Wa2[i] = Wa[(size_t)k*NH + (c << 2) + j];
    }
}

// zero only invalid output rows
__global__ void zero_kernel(float4* __restrict__ out)
{
    int row = blockIdx.y;
    if (g_rowpos[row] >= 0) return;
    int pos = blockIdx.x * 256 + threadIdx.x;
    if (pos < 22500)
        out[(size_t)row * 22500 + pos] = make_float4(0.f, 0.f, 0.f, 0.f);
}

// ---------------- encoder step: HMMA z-GEMM (M=16, N=16/CTA, K=768) ----------------
__global__ void __launch_bounds__(256, 1)
enc_step(const float* __restrict__ bias, const int* __restrict__ elen, int t)
{
    extern __shared__ __nv_bfloat16 smb[];
    __nv_bfloat16* sAhi = smb;
    __nv_bfloat16* sAlo = smb + 16*PAE;
    __nv_bfloat16* sBhi = smb + 2*16*PAE;
    __nv_bfloat16* sBlo = smb + 3*16*PAE;
    float* part = (float*)(smb + 4*16*PAE);   // [8][16 m][16 n]
    float* zs   = part + 8*256;               // [16 n][16 m]

    int tid = threadIdx.x, c = blockIdx.x;
    int w = tid >> 5, lane = tid & 31;
    const float* h_in  = g_h[t & 1];
    const float* c_in  = g_c[t & 1];
    float* h_out = g_h[(t + 1) & 1];
    float* c_out = g_c[(t + 1) & 1];

    // stage x: fp32 -> bf16 hi/lo rows [m=b][k]
    #pragma unroll
    for (int b = 0; b < 16; b++)
        for (int k = tid; k < KE; k += 256) {
            float v = (k < NE) ? g_qemb[(b*NTE + t)*NE + k] : h_in[b*NH + (k - NE)];
            __nv_bfloat16 hi = __float2bfloat16(v);
            sAhi[b*PAE + k] = hi;
            sAlo[b*PAE + k] = __float2bfloat16(v - __bfloat162float(hi));
        }
    // stage W: 16 n-rows x KE, uint4 copies
    {
        const __nv_bfloat16* Wh = g_Wze_hi + (size_t)c*16*KE;
        const __nv_bfloat16* Wl = g_Wze_lo + (size_t)c*16*KE;
        for (int i = tid; i < 16*(KE/8); i += 256) {
            int n = i / (KE/8), kc = i % (KE/8);
            *(uint4*)&sBhi[n*PAE + kc*8] = *(const uint4*)&Wh[(size_t)n*KE + kc*8];
            *(uint4*)&sBlo[n*PAE + kc*8] = *(const uint4*)&Wl[(size_t)n*KE + kc*8];
        }
    }
    __syncthreads();

    uint32_t sb = smem_u32(smb);
    uint32_t aAhi = sb, aAlo = sb + 16*PAE*2;
    uint32_t aBhi = sb + 2*16*PAE*2, aBlo = sb + 3*16*PAE*2;

    float cc[2][4] = {{0.f,0.f,0.f,0.f},{0.f,0.f,0.f,0.f}};
    int kbase = w * (KE/8);
    #pragma unroll
    for (int ks = 0; ks < KE/128; ks++) {     // 6 k-steps of 16
        int kp = kbase + ks*16;
        uint32_t ahi[4], alo[4];
        uint32_t offA = ((lane & 15)*PAE + kp + ((lane >> 4) << 3)) * 2;
        ldmA(ahi, aAhi + offA);
        ldmA(alo, aAlo + offA);
        #pragma unroll
        for (int nf = 0; nf < 2; nf++) {
            uint32_t bhi[2], blo[2];
            uint32_t offB = ((nf*8 + (lane & 7))*PAE + kp + (((lane >> 3) & 1) << 3)) * 2;
            ldmB(bhi, aBhi + offB);
            ldmB(blo, aBlo + offB);
            mma16816(cc[nf], ahi, bhi);
            mma16816(cc[nf], ahi, blo);
            mma16816(cc[nf], alo, bhi);
        }
    }
    {
        int rg = lane >> 2, cg = (lane & 3) * 2;
        #pragma unroll
        for (int nf = 0; nf < 2; nf++) {
            part[w*256 + rg*16 + nf*8 + cg]         = cc[nf][0];
            part[w*256 + rg*16 + nf*8 + cg + 1]     = cc[nf][1];
            part[w*256 + (rg+8)*16 + nf*8 + cg]     = cc[nf][2];
            part[w*256 + (rg+8)*16 + nf*8 + cg + 1] = cc[nf][3];
        }
    }
    __syncthreads();
    {
        int m = tid & 15, n = tid >> 4;
        float sum = 0.f;
        #pragma unroll
        for (int w2 = 0; w2 < 8; w2++) sum += part[w2*256 + m*16 + n];
        zs[n*16 + m] = sum;
    }
    __syncthreads();

    if (tid < 64) {
        int jl = tid >> 4, b = tid & 15;
        int jg = (c << 2) + jl;
        float iv = zs[(jl*4 + 0)*16 + b] + bias[0*NH + jg];
        float jv = zs[(jl*4 + 1)*16 + b] + bias[1*NH + jg];
        float fv = zs[(jl*4 + 2)*16 + b] + bias[2*NH + jg];
        float ov = zs[(jl*4 + 3)*16 + b] + bias[3*NH + jg];
        float cold = c_in[b*NH + jg];
        float c2 = cold * fsig(fv + 1.f) + fsig(iv) * ftanh(jv);
        float h2 = ftanh(c2) * fsig(ov);
        bool valid = t < elen[b];
        float hold = h_in[b*NH + jg];
        h_out[b*NH + jg] = valid ? h2 : hold;
        c_out[b*NH + jg] = valid ? c2 : cold;
        g_encout[((size_t)b*NTE + t)*NH + jg] = valid ? h2 : 0.f;
    }
}

// ---------------- keys = enc_out @ W_mem ----------------
__global__ void keys_kernel(const float* __restrict__ Wm)
{
    extern __shared__ float sm[];
    const int KX = NH, KP = NH + 4;
    float* xs = sm;
    float* ws = sm + 16*KP;
    int tid = threadIdx.x;
    int cn = blockIdx.x;
    int cr = blockIdx.y;

    for (int i = tid; i < 16*KX; i += 256) {
        int rl = i >> 9, k = i & 511;
        xs[rl*KP + k] = g_encout[(cr*16 + rl)*NH + k];
    }
    for (int i = tid; i < 16*KX; i += 256) {
        int k = i >> 4, nl = i & 15;
        ws[nl*KP + k] = Wm[k*NH + cn*16 + nl];
    }
    __syncthreads();

    int nl = tid & 15, rl = tid >> 4;
    float a0 = 0.f, a1 = 0.f, a2 = 0.f, a3 = 0.f;
    const float* xp = xs + rl*KP;
    const float* wp = ws + nl*KP;
    #pragma unroll 8
    for (int k = 0; k < KX; k += 4) {
        float4 a = *(const float4*)(xp + k);
        float4 w = *(const float4*)(wp + k);
        a0 = fmaf(a.x, w.x, a0);
        a1 = fmaf(a.y, w.y, a1);
        a2 = fmaf(a.z, w.z, a2);
        a3 = fmaf(a.w, w.w, a3);
    }
    g_keys[(cr*16 + rl)*NH + cn*16 + nl] = (a0 + a1) + (a2 + a3);
}

// ---------------- decoder LSTM step: HMMA z-GEMM (K=1280) ----------------
__global__ void __launch_bounds__(256, 1)
dec_lstm(const float* __restrict__ bias, int t)
{
    extern __shared__ __nv_bfloat16 smb[];
    __nv_bfloat16* sAhi = smb;
    __nv_bfloat16* sAlo = smb + 16*PAD;
    __nv_bfloat16* sBhi = smb + 2*16*PAD;
    __nv_bfloat16* sBlo = smb + 3*16*PAD;
    float* part = (float*)(smb + 4*16*PAD);
    float* zs   = part + 8*256;

    int tid = threadIdx.x, c = blockIdx.x;
    int w = tid >> 5, lane = tid & 31;
    const float* h_in  = g_h[t & 1];
    const float* c_in  = g_c[t & 1];
    float* h_out = g_h[(t + 1) & 1];
    float* c_out = g_c[(t + 1) & 1];

    #pragma unroll
    for (int b = 0; b < 16; b++)
        for (int k = tid; k < KD; k += 256) {
            float v;
            if (k < NE)           v = g_remb[(b*NTD + t)*NE + k];
            else if (k < NE + NH) v = g_attn[b*NH + (k - NE)];
            else                  v = h_in[b*NH + (k - NE - NH)];
            __nv_bfloat16 hi = __float2bfloat16(v);
            sAhi[b*PAD + k] = hi;
            sAlo[b*PAD + k] = __float2bfloat16(v - __bfloat162float(hi));
        }
    {
        const __nv_bfloat16* Wh = g_Wzd_hi + (size_t)c*16*KD;
        const __nv_bfloat16* Wl = g_Wzd_lo + (size_t)c*16*KD;
        for (int i = tid; i < 16*(KD/8); i += 256) {
            int n = i / (KD/8), kc = i % (KD/8);
            *(uint4*)&sBhi[n*PAD + kc*8] = *(const uint4*)&Wh[(size_t)n*KD + kc*8];
            *(uint4*)&sBlo[n*PAD + kc*8] = *(const uint4*)&Wl[(size_t)n*KD + kc*8];
        }
    }
    __syncthreads();

    uint32_t sb = smem_u32(smb);
    uint32_t aAhi = sb, aAlo = sb + 16*PAD*2;
    uint32_t aBhi = sb + 2*16*PAD*2, aBlo = sb + 3*16*PAD*2;

    float cc[2][4] = {{0.f,0.f,0.f,0.f},{0.f,0.f,0.f,0.f}};
    int kbase = w * (KD/8);
    #pragma unroll
    for (int ks = 0; ks < KD/128; ks++) {    // 10 k-steps
        int kp = kbase + ks*16;
        uint32_t ahi[4], alo[4];
        uint32_t offA = ((lane & 15)*PAD + kp + ((lane >> 4) << 3)) * 2;
        ldmA(ahi, aAhi + offA);
        ldmA(alo, aAlo + offA);
        #pragma unroll
        for (int nf = 0; nf < 2; nf++) {
            uint32_t bhi[2], blo[2];
            uint32_t offB = ((nf*8 + (lane & 7))*PAD + kp + (((lane >> 3) & 1) << 3)) * 2;
            ldmB(bhi, aBhi + offB);
            ldmB(blo, aBlo + offB);
            mma16816(cc[nf], ahi, bhi);
            mma16816(cc[nf], ahi, blo);
            mma16816(cc[nf], alo, bhi);
        }
    }
    {
        int rg = lane >> 2, cg = (lane & 3) * 2;
        #pragma unroll
        for (int nf = 0; nf < 2; nf++) {
            part[w*256 + rg*16 + nf*8 + cg]         = cc[nf][0];
            part[w*256 + rg*16 + nf*8 + cg + 1]     = cc[nf][1];
            part[w*256 + (rg+8)*16 + nf*8 + cg]     = cc[nf][2];
            part[w*256 + (rg+8)*16 + nf*8 + cg + 1] = cc[nf][3];
        }
    }
    __syncthreads();
    {
        int m = tid & 15, n = tid >> 4;
        float sum = 0.f;
        #pragma unroll
        for (int w2 = 0; w2 < 8; w2++) sum += part[w2*256 + m*16 + n];
        zs[n*16 + m] = sum;
    }
    __syncthreads();

    if (tid < 64) {
        int jl = tid >> 4, b = tid & 15;
        int jg = (c << 2) + jl;
        float iv = zs[(jl*4 + 0)*16 + b] + bias[0*NH + jg];
        float jv = zs[(jl*4 + 1)*16 + b] + bias[1*NH + jg];
        float fv = zs[(jl*4 + 2)*16 + b] + bias[2*NH + jg];
        float ov = zs[(jl*4 + 3)*16 + b] + bias[3*NH + jg];
        float cold = c_in[b*NH + jg];
        float c2 = cold * fsig(fv + 1.f) + fsig(iv) * ftanh(jv);
        float h2 = ftanh(c2) * fsig(ov);
        h_out[b*NH + jg] = h2;
        c_out[b*NH + jg] = c2;
    }
}

// ---------------- pq = h2 @ Wq : 128 CTAs x 256 thr ----------------
__global__ void __launch_bounds__(256, 2)
dec_pq(int t)
{
    __shared__ float zp[256*4];
    int tid = threadIdx.x;
    int c = blockIdx.x;
    int n0 = c * 4;
    int bq = tid & 15, ks = tid >> 4;
    const float* h2 = g_h[(t + 1) & 1];

    const float* hp = h2 + bq*NH + ks*32;
    const float4* wq4 = (const float4*)(g_Wq2 + (size_t)c*2048);
    float a0 = 0.f, a1 = 0.f, a2 = 0.f, a3 = 0.f;
    #pragma unroll
    for (int kk = 0; kk < 32; kk++) {
        float x = hp[kk];
        float4 w = __ldg(wq4 + ks*32 + kk);
        a0 = fmaf(x, w.x, a0);
        a1 = fmaf(x, w.y, a1);
        a2 = fmaf(x, w.z, a2);
        a3 = fmaf(x, w.w, a3);
    }
    zp[tid*4 + 0] = a0; zp[tid*4 + 1] = a1;
    zp[tid*4 + 2] = a2; zp[tid*4 + 3] = a3;
    __syncthreads();

    if (tid < 64) {
        int bb = tid >> 2, j = tid & 3;
        float sv = 0.f;
        #pragma unroll
        for (int ss = 0; ss < 16; ss++) sv += zp[(bb + 16*ss)*4 + j];
        g_pq[bb*NH + n0 + j] = sv;
    }
}

// ---------------- scores + softmax + ctx : 16 CTAs x 512 thr ----------------
__global__ void __launch_bounds__(512, 1)
dec_att(const float* __restrict__ vatt, const int* __restrict__ elen, int t)
{
    __shared__ float pqv[NH];
    __shared__ float vsv[NH];
    __shared__ float scv[NTE];

    int tid = threadIdx.x;
    int b = blockIdx.x;

    pqv[tid] = g_pq[b*NH + tid];
    vsv[tid] = vatt[tid];
    __syncthreads();

    int w = tid >> 5, l = tid & 31;
    int len = elen[b];
    #pragma unroll
    for (int r = 0; r < 4; r++) {
        int te = w*4 + r;
        const float* kp = g_keys + ((size_t)b*NTE + te)*NH;
        float p = 0.f;
        #pragma unroll
        for (int j = 0; j < 16; j++) {
            int h = l + 32*j;
            p += vsv[h] * ftanh(kp[h] + pqv[h]);
        }
        #pragma unroll
        for (int off = 16; off > 0; off >>= 1) p += __shfl_xor_sync(0xffffffffu, p, off);
        if (l == 0) scv[te] = (te < len) ? p : NEGV;
    }
    __syncthreads();

    if (tid < 32) {
        float a = scv[tid], b2 = scv[tid + 32];
        float m = fmaxf(a, b2);
        #pragma unroll
        for (int off = 16; off > 0; off >>= 1) m = fmaxf(m, __shfl_xor_sync(0xffffffffu, m, off));
        float e1 = __expf(a - m), e2 = __expf(b2 - m);
        float ssum = e1 + e2;
        #pragma unroll
        for (int off = 16; off > 0; off >>= 1) ssum += __shfl_xor_sync(0xffffffffu, ssum, off);
        float inv = __fdividef(1.f, ssum);
        scv[tid] = e1 * inv; scv[tid + 32] = e2 * inv;
    }
    __syncthreads();

    {
        int h = tid;
        float acc = 0.f;
        const float* ep = g_encout + (size_t)b*NTE*NH + h;
        #pragma unroll 8
        for (int te = 0; te < NTE; te++)
            acc = fmaf(scv[te], ep[(size_t)te*NH], acc);
        g_ctx[b*NH + h] = acc;
    }
}

// ---------------- attn2 = [h2|ctx] @ Wa : 128 CTAs x 256 thr ----------------
__global__ void __launch_bounds__(256, 2)
dec_attn2(int t)
{
    __shared__ float zp[256*4];
    int tid = threadIdx.x;
    int c = blockIdx.x;
    int n0 = c * 4;
    int bq = tid & 15, ks = tid >> 4;
    const float* h2 = g_h[(t + 1) & 1];

    const float* src = (ks < 8) ? (h2 + bq*NH + ks*64)
                                : (g_ctx + bq*NH + (ks - 8)*64);
    const float4* wa4 = (const float4*)(g_Wa2 + (size_t)c*4096);
    float a0 = 0.f, a1 = 0.f, a2 = 0.f, a3 = 0.f;
    #pragma unroll
    for (int kk = 0; kk < 64; kk++) {
        float x = src[kk];
        float4 w = __ldg(wa4 + ks*64 + kk);
        a0 = fmaf(x, w.x, a0);
        a1 = fmaf(x, w.y, a1);
        a2 = fmaf(x, w.z, a2);
        a3 = fmaf(x, w.w, a3);
    }
    zp[tid*4 + 0] = a0; zp[tid*4 + 1] = a1;
    zp[tid*4 + 2] = a2; zp[tid*4 + 3] = a3;
    __syncthreads();

    if (tid < 64) {
        int bb = tid >> 2, j = tid & 3;
        float sv = 0.f;
        #pragma unroll
        for (int ss = 0; ss < 16; ss++) sv += zp[(bb + 16*ss)*4 + j];
        g_attn[bb*NH + n0 + j] = sv;
        int m = g_rowpos[bb*NTD + t];
        if (m >= 0) {
            __nv_bfloat16 hi = __float2bfloat16(sv);
            g_Ahi[m*NH + n0 + j] = hi;
            g_Alo[m*NH + n0 + j] = __float2bfloat16(sv - __bfloat162float(hi));
        }
    }
}

// ---------------- HMMA projection with in-kernel W conversion ----------------
#define PR_LDA 72
#define PROJ_SMEM (4*128*PR_LDA*2)

__global__ void __launch_bounds__(256, 1)
proj_hmma(const float* __restrict__ Wp, float* __restrict__ out)
{
    extern __shared__ __nv_bfloat16 smb[];
    __nv_bfloat16* sAhi = smb;
    __nv_bfloat16* sAlo = smb + 128*PR_LDA;
    __nv_bfloat16* sBhi = smb + 2*128*PR_LDA;
    __nv_bfloat16* sBlo = smb + 3*128*PR_LDA;

    int m0 = blockIdx.x * 128;
    int n0 = blockIdx.y * 128;
    int nr = g_nrows;
    if (m0 >= nr) return;

    int tid = threadIdx.x;
    int wid = tid >> 5, lane = tid & 31;
    int m0w = (wid >> 2) * 64;
    int n0w = (wid & 3) * 32;

    uint32_t sb = smem_u32(smb);
    uint32_t aAhi = sb, aAlo = sb + 128*PR_LDA*2, aBhi = sb + 2*128*PR_LDA*2, aBlo = sb + 3*128*PR_LDA*2;

    float c[4][4][4];
    #pragma unroll
    for (int i = 0; i < 4; i++)
        #pragma unroll
        for (int j = 0; j < 4; j++)
            #pragma unroll
            for (int q = 0; q < 4; q++) c[i][j][q] = 0.f;

    for (int ch = 0; ch < 8; ch++) {
        int k0 = ch * 64;
        for (int i = tid; i < 1024; i += 256) {
            int m = i >> 3, kb = i & 7;
            size_t go = (size_t)(m0 + m)*NH + k0 + kb*8;
            int so = m*PR_LDA + kb*8;
            *(uint4*)&sAhi[so] = *(const uint4*)&g_Ahi[go];
            *(uint4*)&sAlo[so] = *(const uint4*)&g_Alo[go];
        }
        for (int i = tid; i < 4096; i += 256) {
            int n = i & 127, kkp = i >> 7;
            int kk = kkp * 2;
            int nn = n0 + n;
            float w0 = 0.f, w1 = 0.f;
            if (nn < NV) {
                w0 = Wp[(size_t)(k0 + kk)*NV + nn];
                w1 = Wp[(size_t)(k0 + kk + 1)*NV + nn];
            }
            __nv_bfloat16 h0 = __float2bfloat16(w0);
            __nv_bfloat16 h1 = __float2bfloat16(w1);
            float r0 = w0 - __bfloat162float(h0);
            float r1 = w1 - __bfloat162float(h1);
            __nv_bfloat16 l0 = __float2bfloat16(r0);
            __nv_bfloat16 l1 = __float2bfloat16(r1);
            uint32_t hv = (uint32_t)__bfloat16_as_ushort(h0) |
                          ((uint32_t)__bfloat16_as_ushort(h1) << 16);
            uint32_t lv = (uint32_t)__bfloat16_as_ushort(l0) |
                          ((uint32_t)__bfloat16_as_ushort(l1) << 16);
            int so = n*PR_LDA + kk;
            *(uint32_t*)&sBhi[so] = hv;
            *(uint32_t*)&sBlo[so] = lv;
        }
        __syncthreads();

        #pragma unroll
        for (int ksp = 0; ksp < 4; ksp++) {
            int kp = ksp * 16;
            uint32_t ahi[4][4], alo[4][4], bhi[4][2], blo[4][2];
            #pragma unroll
            for (int mt = 0; mt < 4; mt++) {
                uint32_t off = ((m0w + mt*16 + (lane & 15)) * PR_LDA + kp + ((lane >> 4) << 3)) * 2;
                ldmA(ahi[mt], aAhi + off);
                ldmA(alo[mt], aAlo + off);
            }
            #pragma unroll
            for (int nt = 0; nt < 4; nt++) {
                uint32_t off = ((n0w + nt*8 + (lane & 7)) * PR_LDA + kp + (((lane >> 3) & 1) << 3)) * 2;
                ldmB(bhi[nt], aBhi + off);
                ldmB(blo[nt], aBlo + off);
            }
            #pragma unroll
            for (int mt = 0; mt < 4; mt++)
                #pragma unroll
                for (int nt = 0; nt < 4; nt++) {
                    mma16816(c[mt][nt], ahi[mt], bhi[nt]);
                    mma16816(c[mt][nt], ahi[mt], blo[nt]);
                    mma16816(c[mt][nt], alo[mt], bhi[nt]);
                }
        }
        __syncthreads();
    }

    int rg = lane >> 2, cg = (lane & 3) * 2;
    #pragma unroll
    for (int mt = 0; mt < 4; mt++) {
        #pragma unroll
        for (int half = 0; half < 2; half++) {
            int mloc = m0w + mt*16 + rg + half*8;
            int m = m0 + mloc;
            if (m < nr) {
                int orow = g_outrow[m];
                float* obase = out + (size_t)orow*NV;
                #pragma unroll
                for (int nt = 0; nt < 4; nt++) {
                    int nn = n0 + n0w + nt*8 + cg;
                    float v0 = c[mt][nt][half*2 + 0];
                    float v1 = c[mt][nt][half*2 + 1];
                    if (nn + 1 < NV) {
                        *(float2*)(obase + nn) = make_float2(v0, v1);
                    } else if (nn < NV) {
                        obase[nn] = v0;
                    }
                }
            }
        }
    }
}

// ---------------- launch ----------------
extern "C" void kernel_launch(void* const* d_in, const int* in_sizes, int n_in,
                              void* d_out, int out_size)
{
    const int*   enc_in  = (const int*)d_in[0];
    const int*   dec_in  = (const int*)d_in[1];
    const int*   elen    = (const int*)d_in[2];
    const int*   dlen    = (const int*)d_in[3];
    const float* emb     = (const float*)d_in[4];
    const float* W_enc   = (const float*)d_in[5];
    const float* b_enc   = (const float*)d_in[6];
    const float* W_dec   = (const float*)d_in[7];
    const float* b_dec   = (const float*)d_in[8];
    const float* W_mem   = (const float*)d_in[9];
    const float* W_query = (const float*)d_in[10];
    const float* v_att   = (const float*)d_in[11];
    const float* W_attn  = (const float*)d_in[12];
    const float* W_proj  = (const float*)d_in[13];
    float* out = (float*)d_out;

    const int smemE = 4*16*PAE*2 + (8*256 + 256)*4;   // 99,328 + 9,216 = 108,544 B
    const int smemD = 4*16*PAD*2 + (8*256 + 256)*4;   // 164,864 + 9,216 = 174,080 B
    const int smemK = (2*16*(NH + 4)) * 4;            //  66,048 B

    cudaFuncSetAttribute(enc_step,    cudaFuncAttributeMaxDynamicSharedMemorySize, smemE);
    cudaFuncSetAttribute(dec_lstm,    cudaFuncAttributeMaxDynamicSharedMemorySize, smemD);
    cudaFuncSetAttribute(keys_kernel, cudaFuncAttributeMaxDynamicSharedMemorySize, smemK);
    cudaFuncSetAttribute(proj_hmma,   cudaFuncAttributeMaxDynamicSharedMemorySize, PROJ_SMEM);

    prep_kernel<<<256, 256>>>(enc_in, dec_in, dlen, emb);
    permW_kernel<<<1024, 256>>>(W_enc, W_dec, W_query, W_attn);
    zero_kernel<<<dim3(88, 512), 256>>>((float4*)out);

    for (int t = 0; t < NTE; t++)
        enc_step<<<128, 256, smemE>>>(b_enc, elen, t);

    keys_kernel<<<dim3(32, 64), 256, smemK>>>(W_mem);

    for (int t = 0; t < NTD; t++) {
        dec_lstm<<<128, 256, smemD>>>(b_dec, t);
        dec_pq<<<128, 256>>>(t);
        dec_att<<<16, 512>>>(v_att, elen, t);
        dec_attn2<<<128, 256>>>(t);
    }

    proj_hmma<<<dim3(4, 704), 256, PROJ_SMEM>>>(W_proj, out);
}

// round 16
// speedup vs baseline: 1.3333x; 1.3333x over previous
#include <cuda_runtime.h>
#include <cuda_bf16.h>
#include <math.h>
#include <stdint.h>

#define NB 16
#define NTE 64
#define NTD 32
#define NE 256
#define NH 512
#define NG 2048
#define NV 90000
#define NEGV (-1e9f)
#define PX 18

typedef unsigned long long u64;

// ---------------- device scratch ----------------
__device__ float g_qemb[NB*NTE*NE];
__device__ float g_remb[NB*NTD*NE];
__device__ float g_h[2][NB*NH];
__device__ float g_c[2][NB*NH];
__device__ float g_attn[NB*NH];
__device__ float g_encout[NB*NTE*NH];
__device__ float g_keys[NB*NTE*NH];
__device__ float g_pq[NB*NH];
__device__ float g_ctx[NB*NH];
__device__ int   g_outrow[NB*NTD];
__device__ int   g_rowpos[NB*NTD];
__device__ int   g_nrows;
// recurrent weights (h/attn part only), per-CTA contiguous: [(c*K + k)*16 + gl]
__device__ float g_W3e[128*512*16];
__device__ float g_W3d[128*1024*16];
// input-embedding weights: [(c*256 + k)*16 + gl]
__device__ float g_Wxe[128*256*16];
__device__ float g_Wxd[128*256*16];
// precomputed Zx = emb @ Wx: [t][c][g2][b]
__device__ float g_Zxe[NTE*128*16*16];
__device__ float g_Zxd[NTD*128*16*16];
__device__ float g_Wq2[128*512*4];     // [c][k][j]
__device__ float g_Wa2[128*1024*4];    // [c][k][j]
__device__ __nv_bfloat16 g_Ahi[512*NH];
__device__ __nv_bfloat16 g_Alo[512*NH];

// ---------------- fast math ----------------
__device__ __forceinline__ float fsig(float x) {
    return __fdividef(1.f, 1.f + __expf(-x));
}
__device__ __forceinline__ float ftanh(float x) {
    x = fminf(fmaxf(x, -15.f), 15.f);
    float a = __expf(2.f * x);
    return __fdividef(a - 1.f, a + 1.f);
}
__device__ __forceinline__ u64 packdup(float v) {
    u64 r;
    asm("mov.b64 %0, {%1, %1};" : "=l"(r) : "r"(__float_as_uint(v)));
    return r;
}
__device__ __forceinline__ void fma2(u64& d, u64 a, u64 b) {
    asm("fma.rn.f32x2 %0, %1, %2, %0;" : "+l"(d) : "l"(a), "l"(b));
}
__device__ __forceinline__ void unpack2(u64 v, float& lo, float& hi) {
    unsigned l, h;
    asm("mov.b64 {%0, %1}, %2;" : "=r"(l), "=r"(h) : "l"(v));
    lo = __uint_as_float(l); hi = __uint_as_float(h);
}
__device__ __forceinline__ uint32_t smem_u32(const void* p) {
    uint32_t a;
    asm("{ .reg .u64 t; cvta.to.shared.u64 t, %1; cvt.u32.u64 %0, t; }" : "=r"(a) : "l"(p));
    return a;
}

// ---------------- prep ----------------
__global__ void prep_kernel(const int* __restrict__ enc_in, const int* __restrict__ dec_in,
                            const int* __restrict__ dlen, const float* __restrict__ emb)
{
    int idx = blockIdx.x * blockDim.x + threadIdx.x;
    int stride = gridDim.x * blockDim.x;
    for (int i = idx; i < NB*NTE*NE; i += stride) {
        int e = i & (NE - 1); int bt = i >> 8;
        g_qemb[i] = emb[(size_t)enc_in[bt] * NE + e];
    }
    for (int i = idx; i < NB*NTD*NE; i += stride) {
        int e = i & (NE - 1); int bt = i >> 8;
        g_remb[i] = emb[(size_t)dec_in[bt] * NE + e];
    }
    for (int i = idx; i < NB*NH; i += stride) {
        g_h[0][i] = 0.f; g_c[0][i] = 0.f; g_attn[i] = 0.f;
    }
    __nv_bfloat16 z = __float2bfloat16(0.f);
    for (int i = idx; i < 512*NH; i += stride) { g_Ahi[i] = z; g_Alo[i] = z; }
    if (idx == 0) {
        int n = 0;
        for (int b = 0; b < NB; b++) {
            int L = dlen[b]; if (L > NTD) L = NTD; if (L < 0) L = 0;
            for (int t2 = 0; t2 < NTD; t2++) {
                if (t2 < L) { g_outrow[n] = b*NTD + t2; g_rowpos[b*NTD + t2] = n; n++; }
                else g_rowpos[b*NTD + t2] = -1;
            }
        }
        g_nrows = n;
    }
}

// ---------------- permute weights ----------------
// gl = jl*4 + q;  gate = q*512 + c*4 + jl
__global__ void permW_kernel(const float* __restrict__ We, const float* __restrict__ Wd,
                             const float* __restrict__ Wq, const float* __restrict__ Wa)
{
    int idx = blockIdx.x * blockDim.x + threadIdx.x;
    int stride = gridDim.x * blockDim.x;
    // recurrent parts (k offset 256 in original)
    for (int i = idx; i < 128*512*16; i += stride) {
        int gl = i & 15, ck = i >> 4;
        int k = ck & 511, c = ck >> 9;
        int jl = gl >> 2, q = gl & 3;
        g_W3e[i] = We[(size_t)(NE + k)*NG + q*NH + (c << 2) + jl];
    }
    for (int i = idx; i < 128*1024*16; i += stride) {
        int gl = i & 15, ck = i >> 4;
        int k = ck & 1023, c = ck >> 10;
        int jl = gl >> 2, q = gl & 3;
        g_W3d[i] = Wd[(size_t)(NE + k)*NG + q*NH + (c << 2) + jl];
    }
    // embedding parts (k < 256)
    for (int i = idx; i < 128*256*16; i += stride) {
        int gl = i & 15, ck = i >> 4;
        int k = ck & 255, c = ck >> 8;
        int jl = gl >> 2, q = gl & 3;
        g_Wxe[i] = We[(size_t)k*NG + q*NH + (c << 2) + jl];
        g_Wxd[i] = Wd[(size_t)k*NG + q*NH + (c << 2) + jl];
    }
    for (int i = idx; i < 128*512*4; i += stride) {
        int j = i & 3, r = i >> 2;
        int k = r & 511, c = r >> 9;
        g_Wq2[i] = Wq[(size_t)k*NH + (c << 2) + j];
    }
    for (int i = idx; i < 128*1024*4; i += stride) {
        int j = i & 3, r = i >> 2;
        int k = r & 1023, c = r >> 10;
        g_Wa2[i] = Wa[(size_t)k*NH + (c << 2) + j];
    }
}

// zero only invalid output rows
__global__ void zero_kernel(float4* __restrict__ out)
{
    int row = blockIdx.y;
    if (g_rowpos[row] >= 0) return;
    int pos = blockIdx.x * 256 + threadIdx.x;
    if (pos < 22500)
        out[(size_t)row * 22500 + pos] = make_float4(0.f, 0.f, 0.f, 0.f);
}

// ---------------- Zx = emb @ Wx for all t (batched, once) ----------------
// which=0: encoder (g_qemb,g_Wxe,g_Zxe,T=NTE); which=1: decoder
// grid (128, T), 256 thr; thread (gl, s 0..15), k-split 16
__global__ void __launch_bounds__(256, 1)
zx_kernel(int which)
{
    extern __shared__ float sm[];
    float* xs = sm;               // [256][PX]
    float* zp = sm + 256*PX;      // [256][PX]

    const float* emb = which ? g_remb : g_qemb;
    const float* Wx  = which ? g_Wxd  : g_Wxe;
    float* Zx        = which ? g_Zxd  : g_Zxe;
    int T            = which ? NTD    : NTE;

    int tid = threadIdx.x;
    int c = blockIdx.x, t = blockIdx.y;
    int gl = tid & 15, s = tid >> 4;
    int k0 = s * 16;

    for (int i = tid; i < 16*256; i += 256) {
        int b = i >> 8, k = i & 255;
        xs[k*PX + b] = emb[((size_t)b*T + t)*NE + k];
    }

    float wreg[16];
    {
        const float* Wp = Wx + ((size_t)c*256 + k0)*16 + gl;
        #pragma unroll
        for (int kk = 0; kk < 16; kk++) wreg[kk] = __ldg(Wp + kk*16);
    }
    __syncthreads();

    u64 acc[8];
    #pragma unroll
    for (int p = 0; p < 8; p++) acc[p] = 0ULL;
    #pragma unroll
    for (int kk = 0; kk < 16; kk++) {
        u64 w2 = packdup(wreg[kk]);
        const u64* xk = (const u64*)(xs + (k0 + kk)*PX);
        #pragma unroll
        for (int p = 0; p < 8; p++) fma2(acc[p], xk[p], w2);
    }
    #pragma unroll
    for (int p = 0; p < 8; p++) {
        float lo, hi; unpack2(acc[p], lo, hi);
        zp[tid*PX + 2*p]   = lo;
        zp[tid*PX + 2*p+1] = hi;
    }
    __syncthreads();

    {
        int g2 = tid >> 4, b = tid & 15;
        float sum = 0.f;
        #pragma unroll
        for (int ss = 0; ss < 16; ss++) sum += zp[(g2 + 16*ss)*PX + b];
        Zx[(((size_t)t*128 + c)*16 + g2)*16 + b] = sum;
    }
}

// ---------------- encoder step: K=512 (h only), Zx preadded ----------------
__global__ void __launch_bounds__(512, 1)
enc_step(const float* __restrict__ bias, const int* __restrict__ elen, int t)
{
    extern __shared__ float sm[];
    float* xs = sm;                 // [512][PX]
    float* zp = sm + 512*PX;        // [512][PX]
    float* zz = zp + 512*PX;        // [256]

    int tid = threadIdx.x;
    int c = blockIdx.x;
    int gl = tid & 15, s = tid >> 4;   // s 0..31
    int k0 = s * 16;

    const float* h_in  = g_h[t & 1];
    const float* c_in  = g_c[t & 1];
    float* h_out = g_h[(t + 1) & 1];
    float* c_out = g_c[(t + 1) & 1];

    float wreg[16];
    {
        const float* Wp = g_W3e + ((size_t)c*512 + k0)*16 + gl;
        #pragma unroll
        for (int kk = 0; kk < 16; kk++) wreg[kk] = __ldg(Wp + kk*16);
    }

    #pragma unroll
    for (int b = 0; b < 16; b++)
        for (int k = tid; k < 512; k += 512)
            xs[k*PX + b] = h_in[b*NH + k];
    __syncthreads();

    u64 acc[8];
    #pragma unroll
    for (int p = 0; p < 8; p++) acc[p] = 0ULL;
    #pragma unroll
    for (int kk = 0; kk < 16; kk++) {
        u64 w2 = packdup(wreg[kk]);
        const u64* xk = (const u64*)(xs + (k0 + kk)*PX);
        #pragma unroll
        for (int p = 0; p < 8; p++) fma2(acc[p], xk[p], w2);
    }
    #pragma unroll
    for (int p = 0; p < 8; p++) {
        float lo, hi; unpack2(acc[p], lo, hi);
        zp[tid*PX + 2*p]   = lo;
        zp[tid*PX + 2*p+1] = hi;
    }
    __syncthreads();

    if (tid < 256) {
        int g2 = tid >> 4, b = tid & 15;
        float sum = g_Zxe[(((size_t)t*128 + c)*16 + g2)*16 + b]
                  + bias[(g2 & 3)*NH + (c << 2) + (g2 >> 2)];
        #pragma unroll
        for (int ss = 0; ss < 32; ss++) sum += zp[(g2 + 16*ss)*PX + b];
        zz[g2*16 + b] = sum;
    }
    __syncthreads();

    if (tid < 64) {
        int jl = tid >> 4, b = tid & 15;
        int jg = (c << 2) + jl;
        float iv = zz[(jl*4 + 0)*16 + b];
        float jv = zz[(jl*4 + 1)*16 + b];
        float fv = zz[(jl*4 + 2)*16 + b];
        float ov = zz[(jl*4 + 3)*16 + b];
        float cold = c_in[b*NH + jg];
        float c2 = cold * fsig(fv + 1.f) + fsig(iv) * ftanh(jv);
        float h2 = ftanh(c2) * fsig(ov);
        bool valid = t < elen[b];
        float hold = xs[jg*PX + b];
        h_out[b*NH + jg] = valid ? h2 : hold;
        c_out[b*NH + jg] = valid ? c2 : cold;
        g_encout[((size_t)b*NTE + t)*NH + jg] = valid ? h2 : 0.f;
    }
}

// ---------------- keys = enc_out @ W_mem ----------------
__global__ void keys_kernel(const float* __restrict__ Wm)
{
    extern __shared__ float sm[];
    const int KX = NH, KP = NH + 4;
    float* xs = sm;
    float* ws = sm + 16*KP;
    int tid = threadIdx.x;
    int cn = blockIdx.x;
    int cr = blockIdx.y;

    for (int i = tid; i < 16*KX; i += 256) {
        int rl = i >> 9, k = i & 511;
        xs[rl*KP + k] = g_encout[(cr*16 + rl)*NH + k];
    }
    for (int i = tid; i < 16*KX; i += 256) {
        int k = i >> 4, nl = i & 15;
        ws[nl*KP + k] = Wm[k*NH + cn*16 + nl];
    }
    __syncthreads();

    int nl = tid & 15, rl = tid >> 4;
    float a0 = 0.f, a1 = 0.f, a2 = 0.f, a3 = 0.f;
    const float* xp = xs + rl*KP;
    const float* wp = ws + nl*KP;
    #pragma unroll 8
    for (int k = 0; k < KX; k += 4) {
        float4 a = *(const float4*)(xp + k);
        float4 w = *(const float4*)(wp + k);
        a0 = fmaf(a.x, w.x, a0);
        a1 = fmaf(a.y, w.y, a1);
        a2 = fmaf(a.z, w.z, a2);
        a3 = fmaf(a.w, w.w, a3);
    }
    g_keys[(cr*16 + rl)*NH + cn*16 + nl] = (a0 + a1) + (a2 + a3);
}

// ---------------- decoder LSTM step: K=1024 (attn|h), Zx preadded ----------------
__global__ void __launch_bounds__(512, 1)
dec_lstm(const float* __restrict__ bias, int t)
{
    extern __shared__ float sm[];
    float* xs = sm;                 // [1024][PX]
    float* zp = sm + 1024*PX;       // [512][PX]
    float* zz = zp + 512*PX;        // [256]

    int tid = threadIdx.x;
    int c = blockIdx.x;
    int gl = tid & 15, s = tid >> 4;
    int k0 = s * 32;

    const float* h_in  = g_h[t & 1];
    const float* c_in  = g_c[t & 1];
    float* h_out = g_h[(t + 1) & 1];
    float* c_out = g_c[(t + 1) & 1];

    float wreg[32];
    {
        const float* Wp = g_W3d + ((size_t)c*1024 + k0)*16 + gl;
        #pragma unroll
        for (int kk = 0; kk < 32; kk++) wreg[kk] = __ldg(Wp + kk*16);
    }

    #pragma unroll
    for (int b = 0; b < 16; b++)
        for (int k = tid; k < 1024; k += 512) {
            float v = (k < NH) ? g_attn[b*NH + k] : h_in[b*NH + (k - NH)];
            xs[k*PX + b] = v;
        }
    __syncthreads();

    u64 acc[8];
    #pragma unroll
    for (int p = 0; p < 8; p++) acc[p] = 0ULL;
    #pragma unroll
    for (int kk = 0; kk < 32; kk++) {
        u64 w2 = packdup(wreg[kk]);
        const u64* xk = (const u64*)(xs + (k0 + kk)*PX);
        #pragma unroll
        for (int p = 0; p < 8; p++) fma2(acc[p], xk[p], w2);
    }
    #pragma unroll
    for (int p = 0; p < 8; p++) {
        float lo, hi; unpack2(acc[p], lo, hi);
        zp[tid*PX + 2*p]   = lo;
        zp[tid*PX + 2*p+1] = hi;
    }
    __syncthreads();

    if (tid < 256) {
        int g2 = tid >> 4, b = tid & 15;
        float sum = g_Zxd[(((size_t)t*128 + c)*16 + g2)*16 + b]
                  + bias[(g2 & 3)*NH + (c << 2) + (g2 >> 2)];
        #pragma unroll
        for (int ss = 0; ss < 32; ss++) sum += zp[(g2 + 16*ss)*PX + b];
        zz[g2*16 + b] = sum;
    }
    __syncthreads();

    if (tid < 64) {
        int jl = tid >> 4, b = tid & 15;
        int jg = (c << 2) + jl;
        float iv = zz[(jl*4 + 0)*16 + b];
        float jv = zz[(jl*4 + 1)*16 + b];
        float fv = zz[(jl*4 + 2)*16 + b];
        float ov = zz[(jl*4 + 3)*16 + b];
        float cold = c_in[b*NH + jg];
        float c2 = cold * fsig(fv + 1.f) + fsig(iv) * ftanh(jv);
        float h2 = ftanh(c2) * fsig(ov);
        h_out[b*NH + jg] = h2;
        c_out[b*NH + jg] = c2;
    }
}

// ---------------- pq = h2 @ Wq : 128 CTAs x 256 thr ----------------
__global__ void __launch_bounds__(256, 1)
dec_pq(int t)
{
    extern __shared__ float sm[];
    float* zp = sm;   // [256*4]
    int tid = threadIdx.x;
    int c = blockIdx.x;
    int n0 = c * 4;
    int bq = tid & 15, ks = tid >> 4;
    const float* h2 = g_h[(t + 1) & 1];

    const float* hp = h2 + bq*NH + ks*32;
    const float4* wq4 = (const float4*)(g_Wq2 + (size_t)c*2048);
    float a0 = 0.f, a1 = 0.f, a2 = 0.f, a3 = 0.f;
    #pragma unroll
    for (int kk = 0; kk < 32; kk++) {
        float x = hp[kk];
        float4 w = __ldg(wq4 + ks*32 + kk);
        a0 = fmaf(x, w.x, a0);
        a1 = fmaf(x, w.y, a1);
        a2 = fmaf(x, w.z, a2);
        a3 = fmaf(x, w.w, a3);
    }
    zp[tid*4 + 0] = a0; zp[tid*4 + 1] = a1;
    zp[tid*4 + 2] = a2; zp[tid*4 + 3] = a3;
    __syncthreads();

    if (tid < 64) {
        int bb = tid >> 2, j = tid & 3;
        float sv = 0.f;
        #pragma unroll
        for (int ss = 0; ss < 16; ss++) sv += zp[(bb + 16*ss)*4 + j];
        g_pq[bb*NH + n0 + j] = sv;
    }
}

// ---------------- scores + softmax + ctx : 16 CTAs x 512 thr ----------------
__global__ void __launch_bounds__(512, 1)
dec_att(const float* __restrict__ vatt, const int* __restrict__ elen, int t)
{
    extern __shared__ float sm[];
    float* pqv = sm;          // [512]
    float* vsv = sm + 512;    // [512]
    float* scv = sm + 1024;   // [64]

    int tid = threadIdx.x;
    int b = blockIdx.x;

    pqv[tid] = g_pq[b*NH + tid];
    vsv[tid] = vatt[tid];
    __syncthreads();

    int w = tid >> 5, l = tid & 31;
    int len = elen[b];
    #pragma unroll
    for (int r = 0; r < 4; r++) {
        int te = w*4 + r;
        const float* kp = g_keys + ((size_t)b*NTE + te)*NH;
        float p = 0.f;
        #pragma unroll
        for (int j = 0; j < 16; j++) {
            int h = l + 32*j;
            p += vsv[h] * ftanh(kp[h] + pqv[h]);
        }
        #pragma unroll
        for (int off = 16; off > 0; off >>= 1) p += __shfl_xor_sync(0xffffffffu, p, off);
        if (l == 0) scv[te] = (te < len) ? p : NEGV;
    }
    __syncthreads();

    if (tid < 32) {
        float a = scv[tid], b2 = scv[tid + 32];
        float m = fmaxf(a, b2);
        #pragma unroll
        for (int off = 16; off > 0; off >>= 1) m = fmaxf(m, __shfl_xor_sync(0xffffffffu, m, off));
        float e1 = __expf(a - m), e2 = __expf(b2 - m);
        float ssum = e1 + e2;
        #pragma unroll
        for (int off = 16; off > 0; off >>= 1) ssum += __shfl_xor_sync(0xffffffffu, ssum, off);
        float inv = __fdividef(1.f, ssum);
        scv[tid] = e1 * inv; scv[tid + 32] = e2 * inv;
    }
    __syncthreads();

    {
        int h = tid;
        float acc = 0.f;
        const float* ep = g_encout + (size_t)b*NTE*NH + h;
        #pragma unroll 8
        for (int te = 0; te < NTE; te++)
            acc = fmaf(scv[te], ep[(size_t)te*NH], acc);
        g_ctx[b*NH + h] = acc;
    }
}

// ---------------- attn2 = [h2|ctx] @ Wa : 128 CTAs x 256 thr ----------------
__global__ void __launch_bounds__(256, 1)
dec_attn2(int t)
{
    extern __shared__ float sm[];
    float* zp = sm;
    int tid = threadIdx.x;
    int c = blockIdx.x;
    int n0 = c * 4;
    int bq = tid & 15, ks = tid >> 4;
    const float* h2 = g_h[(t + 1) & 1];

    const float* src = (ks < 8) ? (h2 + bq*NH + ks*64)
                                : (g_ctx + bq*NH + (ks - 8)*64);
    const float4* wa4 = (const float4*)(g_Wa2 + (size_t)c*4096);
    float a0 = 0.f, a1 = 0.f, a2 = 0.f, a3 = 0.f;
    #pragma unroll
    for (int kk = 0; kk < 64; kk++) {
        float x = src[kk];
        float4 w = __ldg(wa4 + ks*64 + kk);
        a0 = fmaf(x, w.x, a0);
        a1 = fmaf(x, w.y, a1);
        a2 = fmaf(x, w.z, a2);
        a3 = fmaf(x, w.w, a3);
    }
    zp[tid*4 + 0] = a0; zp[tid*4 + 1] = a1;
    zp[tid*4 + 2] = a2; zp[tid*4 + 3] = a3;
    __syncthreads();

    if (tid < 64) {
        int bb = tid >> 2, j = tid & 3;
        float sv = 0.f;
        #pragma unroll
        for (int ss = 0; ss < 16; ss++) sv += zp[(bb + 16*ss)*4 + j];
        g_attn[bb*NH + n0 + j] = sv;
        int m = g_rowpos[bb*NTD + t];
        if (m >= 0) {
            __nv_bfloat16 hi = __float2bfloat16(sv);
            g_Ahi[m*NH + n0 + j] = hi;
            g_Alo[m*NH + n0 + j] = __float2bfloat16(sv - __bfloat162float(hi));
        }
    }
}

// ---------------- HMMA projection (r10-proven) ----------------
#define PR_LDA 72
#define PROJ_SMEM (4*128*PR_LDA*2)

__device__ __forceinline__ void ldmA(uint32_t* a, uint32_t addr) {
    asm volatile("ldmatrix.sync.aligned.m8n8.x4.shared.b16 {%0,%1,%2,%3}, [%4];"
                 : "=r"(a[0]), "=r"(a[1]), "=r"(a[2]), "=r"(a[3]) : "r"(addr));
}
__device__ __forceinline__ void ldmB(uint32_t* b, uint32_t addr) {
    asm volatile("ldmatrix.sync.aligned.m8n8.x2.shared.b16 {%0,%1}, [%2];"
                 : "=r"(b[0]), "=r"(b[1]) : "r"(addr));
}
__device__ __forceinline__ void mma16816(float* c, const uint32_t* a, const uint32_t* b) {
    asm volatile("mma.sync.aligned.m16n8k16.row.col.f32.bf16.bf16.f32 "
                 "{%0,%1,%2,%3}, {%4,%5,%6,%7}, {%8,%9}, {%0,%1,%2,%3};"
                 : "+f"(c[0]), "+f"(c[1]), "+f"(c[2]), "+f"(c[3])
                 : "r"(a[0]), "r"(a[1]), "r"(a[2]), "r"(a[3]), "r"(b[0]), "r"(b[1]));
}

__global__ void __launch_bounds__(256, 1)
proj_hmma(const float* __restrict__ Wp, float* __restrict__ out)
{
    extern __shared__ __nv_bfloat16 smb[];
    __nv_bfloat16* sAhi = smb;
    __nv_bfloat16* sAlo = smb + 128*PR_LDA;
    __nv_bfloat16* sBhi = smb + 2*128*PR_LDA;
    __nv_bfloat16* sBlo = smb + 3*128*PR_LDA;

    int m0 = blockIdx.x * 128;
    int n0 = blockIdx.y * 128;
    int nr = g_nrows;
    if (m0 >= nr) return;

    int tid = threadIdx.x;
    int wid = tid >> 5, lane = tid & 31;
    int m0w = (wid >> 2) * 64;
    int n0w = (wid & 3) * 32;

    uint32_t sb = smem_u32(smb);
    uint32_t aAhi = sb, aAlo = sb + 128*PR_LDA*2, aBhi = sb + 2*128*PR_LDA*2, aBlo = sb + 3*128*PR_LDA*2;

    float c[4][4][4];
    #pragma unroll
    for (int i = 0; i < 4; i++)
        #pragma unroll
        for (int j = 0; j < 4; j++)
            #pragma unroll
            for (int q = 0; q < 4; q++) c[i][j][q] = 0.f;

    for (int ch = 0; ch < 8; ch++) {
        int k0 = ch * 64;
        for (int i = tid; i < 1024; i += 256) {
            int m = i >> 3, kb = i & 7;
            size_t go = (size_t)(m0 + m)*NH + k0 + kb*8;
            int so = m*PR_LDA + kb*8;
            *(uint4*)&sAhi[so] = *(const uint4*)&g_Ahi[go];
            *(uint4*)&sAlo[so] = *(const uint4*)&g_Alo[go];
        }
        for (int i = tid; i < 4096; i += 256) {
            int n = i & 127, kkp = i >> 7;
            int kk = kkp * 2;
            int nn = n0 + n;
            float w0 = 0.f, w1 = 0.f;
            if (nn < NV) {
                w0 = Wp[(size_t)(k0 + kk)*NV + nn];
                w1 = Wp[(size_t)(k0 + kk + 1)*NV + nn];
            }
            __nv_bfloat16 h0 = __float2bfloat16(w0);
            __nv_bfloat16 h1 = __float2bfloat16(w1);
            float r0 = w0 - __bfloat162float(h0);
            float r1 = w1 - __bfloat162float(h1);
            __nv_bfloat16 l0 = __float2bfloat16(r0);
            __nv_bfloat16 l1 = __float2bfloat16(r1);
            uint32_t hv = (uint32_t)__bfloat16_as_ushort(h0) |
                          ((uint32_t)__bfloat16_as_ushort(h1) << 16);
            uint32_t lv = (uint32_t)__bfloat16_as_ushort(l0) |
                          ((uint32_t)__bfloat16_as_ushort(l1) << 16);
            int so = n*PR_LDA + kk;
            *(uint32_t*)&sBhi[so] = hv;
            *(uint32_t*)&sBlo[so] = lv;
        }
        __syncthreads();

        #pragma unroll
        for (int ksp = 0; ksp < 4; ksp++) {
            int kp = ksp * 16;
            uint32_t ahi[4][4], alo[4][4], bhi[4][2], blo[4][2];
            #pragma unroll
            for (int mt = 0; mt < 4; mt++) {
                uint32_t off = ((m0w + mt*16 + (lane & 15)) * PR_LDA + kp + ((lane >> 4) << 3)) * 2;
                ldmA(ahi[mt], aAhi + off);
                ldmA(alo[mt], aAlo + off);
            }
            #pragma unroll
            for (int nt = 0; nt < 4; nt++) {
                uint32_t off = ((n0w + nt*8 + (lane & 7)) * PR_LDA + kp + (((lane >> 3) & 1) << 3)) * 2;
                ldmB(bhi[nt], aBhi + off);
                ldmB(blo[nt], aBlo + off);
            }
            #pragma unroll
            for (int mt = 0; mt < 4; mt++)
                #pragma unroll
                for (int nt = 0; nt < 4; nt++) {
                    mma16816(c[mt][nt], ahi[mt], bhi[nt]);
                    mma16816(c[mt][nt], ahi[mt], blo[nt]);
                    mma16816(c[mt][nt], alo[mt], bhi[nt]);
                }
        }
        __syncthreads();
    }

    int rg = lane >> 2, cg = (lane & 3) * 2;
    #pragma unroll
    for (int mt = 0; mt < 4; mt++) {
        #pragma unroll
        for (int half = 0; half < 2; half++) {
            int mloc = m0w + mt*16 + rg + half*8;
            int m = m0 + mloc;
            if (m < nr) {
                int orow = g_outrow[m];
                float* obase = out + (size_t)orow*NV;
                #pragma unroll
                for (int nt = 0; nt < 4; nt++) {
                    int nn = n0 + n0w + nt*8 + cg;
                    float v0 = c[mt][nt][half*2 + 0];
                    float v1 = c[mt][nt][half*2 + 1];
                    if (nn + 1 < NV) {
                        *(float2*)(obase + nn) = make_float2(v0, v1);
                    } else if (nn < NV) {
                        obase[nn] = v0;
                    }
                }
            }
        }
    }
}

// ---------------- launch ----------------
extern "C" void kernel_launch(void* const* d_in, const int* in_sizes, int n_in,
                              void* d_out, int out_size)
{
    const int*   enc_in  = (const int*)d_in[0];
    const int*   dec_in  = (const int*)d_in[1];
    const int*   elen    = (const int*)d_in[2];
    const int*   dlen    = (const int*)d_in[3];
    const float* emb     = (const float*)d_in[4];
    const float* W_enc   = (const float*)d_in[5];
    const float* b_enc   = (const float*)d_in[6];
    const float* W_dec   = (const float*)d_in[7];
    const float* b_dec   = (const float*)d_in[8];
    const float* W_mem   = (const float*)d_in[9];
    const float* W_query = (const float*)d_in[10];
    const float* v_att   = (const float*)d_in[11];
    const float* W_attn  = (const float*)d_in[12];
    const float* W_proj  = (const float*)d_in[13];
    float* out = (float*)d_out;

    // uniform dynamic smem across ALL recurrent-loop kernels: no carveout reconfig
    const int SMEM_UNI = (1024*PX + 512*PX + 256) * 4;   // 111,616 B

    cudaFuncSetAttribute(zx_kernel,   cudaFuncAttributeMaxDynamicSharedMemorySize, SMEM_UNI);
    cudaFuncSetAttribute(enc_step,    cudaFuncAttributeMaxDynamicSharedMemorySize, SMEM_UNI);
    cudaFuncSetAttribute(dec_lstm,    cudaFuncAttributeMaxDynamicSharedMemorySize, SMEM_UNI);
    cudaFuncSetAttribute(dec_pq,      cudaFuncAttributeMaxDynamicSharedMemorySize, SMEM_UNI);
    cudaFuncSetAttribute(dec_att,     cudaFuncAttributeMaxDynamicSharedMemorySize, SMEM_UNI);
    cudaFuncSetAttribute(dec_attn2,   cudaFuncAttributeMaxDynamicSharedMemorySize, SMEM_UNI);
    cudaFuncSetAttribute(keys_kernel, cudaFuncAttributeMaxDynamicSharedMemorySize, SMEM_UNI);
    cudaFuncSetAttribute(proj_hmma,   cudaFuncAttributeMaxDynamicSharedMemorySize, PROJ_SMEM);
    // pin carveout to max-shared for everything so the SM config never changes
    cudaFuncSetAttribute(prep_kernel, cudaFuncAttributePreferredSharedMemoryCarveout, 100);
    cudaFuncSetAttribute(permW_kernel,cudaFuncAttributePreferredSharedMemoryCarveout, 100);
    cudaFuncSetAttribute(zero_kernel, cudaFuncAttributePreferredSharedMemoryCarveout, 100);
    cudaFuncSetAttribute(zx_kernel,   cudaFuncAttributePreferredSharedMemoryCarveout, 100);
    cudaFuncSetAttribute(enc_step,    cudaFuncAttributePreferredSharedMemoryCarveout, 100);
    cudaFuncSetAttribute(dec_lstm,    cudaFuncAttributePreferredSharedMemoryCarveout, 100);
    cudaFuncSetAttribute(dec_pq,      cudaFuncAttributePreferredSharedMemoryCarveout, 100);
    cudaFuncSetAttribute(dec_att,     cudaFuncAttributePreferredSharedMemoryCarveout, 100);
    cudaFuncSetAttribute(dec_attn2,   cudaFuncAttributePreferredSharedMemoryCarveout, 100);
    cudaFuncSetAttribute(keys_kernel, cudaFuncAttributePreferredSharedMemoryCarveout, 100);
    cudaFuncSetAttribute(proj_hmma,   cudaFuncAttributePreferredSharedMemoryCarveout, 100);

    prep_kernel<<<256, 256>>>(enc_in, dec_in, dlen, emb);
    permW_kernel<<<1024, 256>>>(W_enc, W_dec, W_query, W_attn);
    zero_kernel<<<dim3(88, 512), 256>>>((float4*)out);
    zx_kernel<<<dim3(128, NTE), 256, SMEM_UNI>>>(0);
    zx_kernel<<<dim3(128, NTD), 256, SMEM_UNI>>>(1);

    for (int t = 0; t < NTE; t++)
        enc_step<<<128, 512, SMEM_UNI>>>(b_enc, elen, t);

    keys_kernel<<<dim3(32, 64), 256, SMEM_UNI>>>(W_mem);

    for (int t = 0; t < NTD; t++) {
        dec_lstm<<<128, 512, SMEM_UNI>>>(b_dec, t);
        dec_pq<<<128, 256, SMEM_UNI>>>(t);
        dec_att<<<16, 512, SMEM_UNI>>>(v_att, elen, t);
        dec_attn2<<<128, 256, SMEM_UNI>>>(t);
    }

    proj_hmma<<<dim3(4, 704), 256, PROJ_SMEM>>>(W_proj, out);
}

// round 17
// speedup vs baseline: 1.3989x; 1.0492x over previous
#include <cuda_runtime.h>
#include <cuda_bf16.h>
#include <math.h>
#include <stdint.h>

#define NB 16
#define NTE 64
#define NTD 32
#define NE 256
#define NH 512
#define NG 2048
#define NV 90000
#define NEGV (-1e9f)
#define PX 18

typedef unsigned long long u64;

// ---------------- device scratch ----------------
__device__ float g_qemb[NB*NTE*NE];
__device__ float g_remb[NB*NTD*NE];
__device__ float g_h[2][NB*NH];
__device__ float g_c[2][NB*NH];
__device__ float g_attn[NB*NH];
__device__ float g_encout[NB*NTE*NH];
__device__ float g_keys[NB*NTE*NH];
__device__ float g_pq[NB*NH];
__device__ float g_ctx[NB*NH];
__device__ int   g_outrow[NB*NTD];
__device__ int   g_rowpos[NB*NTD];
__device__ int   g_nrows;
// recurrent weights (h/attn part only), per-CTA contiguous: [(c*K + k)*16 + gl]
__device__ float g_W3e[128*512*16];
__device__ float g_W3d[128*1024*16];
// input-embedding weights: [(c*256 + k)*16 + gl]
__device__ float g_Wxe[128*256*16];
__device__ float g_Wxd[128*256*16];
// precomputed Zx = emb @ Wx: [t][c][g2][b]
__device__ float g_Zxe[NTE*128*16*16];
__device__ float g_Zxd[NTD*128*16*16];
__device__ float g_Wq2[128*512*4];     // [c][k][j]
__device__ float g_Wa2[128*1024*4];    // [c][k][j]
__device__ __nv_bfloat16 g_Ahi[512*NH];
__device__ __nv_bfloat16 g_Alo[512*NH];

// ---------------- fast math ----------------
__device__ __forceinline__ float fsig(float x) {
    return __fdividef(1.f, 1.f + __expf(-x));
}
__device__ __forceinline__ float ftanh(float x) {
    x = fminf(fmaxf(x, -15.f), 15.f);
    float a = __expf(2.f * x);
    return __fdividef(a - 1.f, a + 1.f);
}
__device__ __forceinline__ u64 packdup(float v) {
    u64 r;
    asm("mov.b64 %0, {%1, %1};" : "=l"(r) : "r"(__float_as_uint(v)));
    return r;
}
__device__ __forceinline__ void fma2(u64& d, u64 a, u64 b) {
    asm("fma.rn.f32x2 %0, %1, %2, %0;" : "+l"(d) : "l"(a), "l"(b));
}
__device__ __forceinline__ void unpack2(u64 v, float& lo, float& hi) {
    unsigned l, h;
    asm("mov.b64 {%0, %1}, %2;" : "=r"(l), "=r"(h) : "l"(v));
    lo = __uint_as_float(l); hi = __uint_as_float(h);
}
__device__ __forceinline__ uint32_t smem_u32(const void* p) {
    uint32_t a;
    asm("{ .reg .u64 t; cvta.to.shared.u64 t, %1; cvt.u32.u64 %0, t; }" : "=r"(a) : "l"(p));
    return a;
}

// ---------------- prep ----------------
__global__ void prep_kernel(const int* __restrict__ enc_in, const int* __restrict__ dec_in,
                            const int* __restrict__ dlen, const float* __restrict__ emb)
{
    int idx = blockIdx.x * blockDim.x + threadIdx.x;
    int stride = gridDim.x * blockDim.x;
    for (int i = idx; i < NB*NTE*NE; i += stride) {
        int e = i & (NE - 1); int bt = i >> 8;
        g_qemb[i] = emb[(size_t)enc_in[bt] * NE + e];
    }
    for (int i = idx; i < NB*NTD*NE; i += stride) {
        int e = i & (NE - 1); int bt = i >> 8;
        g_remb[i] = emb[(size_t)dec_in[bt] * NE + e];
    }
    for (int i = idx; i < NB*NH; i += stride) {
        g_h[0][i] = 0.f; g_c[0][i] = 0.f; g_attn[i] = 0.f;
    }
    __nv_bfloat16 z = __float2bfloat16(0.f);
    for (int i = idx; i < 512*NH; i += stride) { g_Ahi[i] = z; g_Alo[i] = z; }
    if (idx == 0) {
        int n = 0;
        for (int b = 0; b < NB; b++) {
            int L = dlen[b]; if (L > NTD) L = NTD; if (L < 0) L = 0;
            for (int t2 = 0; t2 < NTD; t2++) {
                if (t2 < L) { g_outrow[n] = b*NTD + t2; g_rowpos[b*NTD + t2] = n; n++; }
                else g_rowpos[b*NTD + t2] = -1;
            }
        }
        g_nrows = n;
    }
}

// ---------------- permute weights ----------------
// gl = jl*4 + q;  gate = q*512 + c*4 + jl
__global__ void permW_kernel(const float* __restrict__ We, const float* __restrict__ Wd,
                             const float* __restrict__ Wq, const float* __restrict__ Wa)
{
    int idx = blockIdx.x * blockDim.x + threadIdx.x;
    int stride = gridDim.x * blockDim.x;
    // recurrent parts (k offset 256 in original)
    for (int i = idx; i < 128*512*16; i += stride) {
        int gl = i & 15, ck = i >> 4;
        int k = ck & 511, c = ck >> 9;
        int jl = gl >> 2, q = gl & 3;
        g_W3e[i] = We[(size_t)(NE + k)*NG + q*NH + (c << 2) + jl];
    }
    for (int i = idx; i < 128*1024*16; i += stride) {
        int gl = i & 15, ck = i >> 4;
        int k = ck & 1023, c = ck >> 10;
        int jl = gl >> 2, q = gl & 3;
        g_W3d[i] = Wd[(size_t)(NE + k)*NG + q*NH + (c << 2) + jl];
    }
    // embedding parts (k < 256)
    for (int i = idx; i < 128*256*16; i += stride) {
        int gl = i & 15, ck = i >> 4;
        int k = ck & 255, c = ck >> 8;
        int jl = gl >> 2, q = gl & 3;
        g_Wxe[i] = We[(size_t)k*NG + q*NH + (c << 2) + jl];
        g_Wxd[i] = Wd[(size_t)k*NG + q*NH + (c << 2) + jl];
    }
    for (int i = idx; i < 128*512*4; i += stride) {
        int j = i & 3, r = i >> 2;
        int k = r & 511, c = r >> 9;
        g_Wq2[i] = Wq[(size_t)k*NH + (c << 2) + j];
    }
    for (int i = idx; i < 128*1024*4; i += stride) {
        int j = i & 3, r = i >> 2;
        int k = r & 1023, c = r >> 10;
        g_Wa2[i] = Wa[(size_t)k*NH + (c << 2) + j];
    }
}

// zero only invalid output rows
__global__ void zero_kernel(float4* __restrict__ out)
{
    int row = blockIdx.y;
    if (g_rowpos[row] >= 0) return;
    int pos = blockIdx.x * 256 + threadIdx.x;
    if (pos < 22500)
        out[(size_t)row * 22500 + pos] = make_float4(0.f, 0.f, 0.f, 0.f);
}

// ---------------- Zx = emb @ Wx, batched: 8 timesteps per CTA ----------------
// which=0: encoder; which=1: decoder. grid (128, T/8), 256 thr.
__global__ void __launch_bounds__(256, 1)
zx_kernel(int which)
{
    extern __shared__ float sm[];
    float* xs = sm;               // [256][PX]
    float* zp = sm + 256*PX;      // [256][PX]

    const float* emb = which ? g_remb : g_qemb;
    const float* Wx  = which ? g_Wxd  : g_Wxe;
    float* Zx        = which ? g_Zxd  : g_Zxe;
    int T            = which ? NTD    : NTE;

    int tid = threadIdx.x;
    int c = blockIdx.x, t0 = blockIdx.y * 8;
    int gl = tid & 15, s = tid >> 4;
    int k0 = s * 16;

    float wreg[16];
    {
        const float* Wp = Wx + ((size_t)c*256 + k0)*16 + gl;
        #pragma unroll
        for (int kk = 0; kk < 16; kk++) wreg[kk] = __ldg(Wp + kk*16);
    }

    for (int tt = 0; tt < 8; tt++) {
        int t = t0 + tt;
        for (int i = tid; i < 16*256; i += 256) {
            int b = i >> 8, k = i & 255;
            xs[k*PX + b] = emb[((size_t)b*T + t)*NE + k];
        }
        __syncthreads();

        u64 acc[8];
        #pragma unroll
        for (int p = 0; p < 8; p++) acc[p] = 0ULL;
        #pragma unroll
        for (int kk = 0; kk < 16; kk++) {
            u64 w2 = packdup(wreg[kk]);
            const u64* xk = (const u64*)(xs + (k0 + kk)*PX);
            #pragma unroll
            for (int p = 0; p < 8; p++) fma2(acc[p], xk[p], w2);
        }
        #pragma unroll
        for (int p = 0; p < 8; p++) {
            float lo, hi; unpack2(acc[p], lo, hi);
            zp[tid*PX + 2*p]   = lo;
            zp[tid*PX + 2*p+1] = hi;
        }
        __syncthreads();

        if (tid < 256) {
            int g2 = tid >> 4, b = tid & 15;
            float sum = 0.f;
            #pragma unroll
            for (int ss = 0; ss < 16; ss++) sum += zp[(g2 + 16*ss)*PX + b];
            Zx[(((size_t)t*128 + c)*16 + g2)*16 + b] = sum;
        }
        __syncthreads();
    }
}

// ---------------- encoder step: K=512 (h only), Zx preadded ----------------
__global__ void __launch_bounds__(512, 1)
enc_step(const float* __restrict__ bias, const int* __restrict__ elen, int t)
{
    extern __shared__ float sm[];
    float* xs = sm;                 // [512][PX]
    float* zp = sm + 512*PX;        // [512][PX]
    float* zz = zp + 512*PX;        // [256]

    int tid = threadIdx.x;
    int c = blockIdx.x;
    int gl = tid & 15, s = tid >> 4;   // s 0..31
    int k0 = s * 16;

    const float* h_in  = g_h[t & 1];
    const float* c_in  = g_c[t & 1];
    float* h_out = g_h[(t + 1) & 1];
    float* c_out = g_c[(t + 1) & 1];

    float wreg[16];
    {
        const float* Wp = g_W3e + ((size_t)c*512 + k0)*16 + gl;
        #pragma unroll
        for (int kk = 0; kk < 16; kk++) wreg[kk] = __ldg(Wp + kk*16);
    }

    #pragma unroll
    for (int b = 0; b < 16; b++)
        for (int k = tid; k < 512; k += 512)
            xs[k*PX + b] = h_in[b*NH + k];
    __syncthreads();

    u64 acc[8];
    #pragma unroll
    for (int p = 0; p < 8; p++) acc[p] = 0ULL;
    #pragma unroll
    for (int kk = 0; kk < 16; kk++) {
        u64 w2 = packdup(wreg[kk]);
        const u64* xk = (const u64*)(xs + (k0 + kk)*PX);
        #pragma unroll
        for (int p = 0; p < 8; p++) fma2(acc[p], xk[p], w2);
    }
    #pragma unroll
    for (int p = 0; p < 8; p++) {
        float lo, hi; unpack2(acc[p], lo, hi);
        zp[tid*PX + 2*p]   = lo;
        zp[tid*PX + 2*p+1] = hi;
    }
    __syncthreads();

    if (tid < 256) {
        int g2 = tid >> 4, b = tid & 15;
        float sum = g_Zxe[(((size_t)t*128 + c)*16 + g2)*16 + b]
                  + bias[(g2 & 3)*NH + (c << 2) + (g2 >> 2)];
        #pragma unroll
        for (int ss = 0; ss < 32; ss++) sum += zp[(g2 + 16*ss)*PX + b];
        zz[g2*16 + b] = sum;
    }
    __syncthreads();

    if (tid < 64) {
        int jl = tid >> 4, b = tid & 15;
        int jg = (c << 2) + jl;
        float iv = zz[(jl*4 + 0)*16 + b];
        float jv = zz[(jl*4 + 1)*16 + b];
        float fv = zz[(jl*4 + 2)*16 + b];
        float ov = zz[(jl*4 + 3)*16 + b];
        float cold = c_in[b*NH + jg];
        float c2 = cold * fsig(fv + 1.f) + fsig(iv) * ftanh(jv);
        float h2 = ftanh(c2) * fsig(ov);
        bool valid = t < elen[b];
        float hold = xs[jg*PX + b];
        h_out[b*NH + jg] = valid ? h2 : hold;
        c_out[b*NH + jg] = valid ? c2 : cold;
        g_encout[((size_t)b*NTE + t)*NH + jg] = valid ? h2 : 0.f;
    }
}

// ---------------- keys = enc_out @ W_mem ----------------
__global__ void keys_kernel(const float* __restrict__ Wm)
{
    extern __shared__ float sm[];
    const int KX = NH, KP = NH + 4;
    float* xs = sm;
    float* ws = sm + 16*KP;
    int tid = threadIdx.x;
    int cn = blockIdx.x;
    int cr = blockIdx.y;

    for (int i = tid; i < 16*KX; i += 256) {
        int rl = i >> 9, k = i & 511;
        xs[rl*KP + k] = g_encout[(cr*16 + rl)*NH + k];
    }
    for (int i = tid; i < 16*KX; i += 256) {
        int k = i >> 4, nl = i & 15;
        ws[nl*KP + k] = Wm[k*NH + cn*16 + nl];
    }
    __syncthreads();

    int nl = tid & 15, rl = tid >> 4;
    float a0 = 0.f, a1 = 0.f, a2 = 0.f, a3 = 0.f;
    const float* xp = xs + rl*KP;
    const float* wp = ws + nl*KP;
    #pragma unroll 8
    for (int k = 0; k < KX; k += 4) {
        float4 a = *(const float4*)(xp + k);
        float4 w = *(const float4*)(wp + k);
        a0 = fmaf(a.x, w.x, a0);
        a1 = fmaf(a.y, w.y, a1);
        a2 = fmaf(a.z, w.z, a2);
        a3 = fmaf(a.w, w.w, a3);
    }
    g_keys[(cr*16 + rl)*NH + cn*16 + nl] = (a0 + a1) + (a2 + a3);
}

// ---------------- decoder LSTM step: K=1024 (attn|h), Zx preadded ----------------
__global__ void __launch_bounds__(512, 1)
dec_lstm(const float* __restrict__ bias, int t)
{
    extern __shared__ float sm[];
    float* xs = sm;                 // [1024][PX]
    float* zp = sm + 1024*PX;       // [512][PX]
    float* zz = zp + 512*PX;        // [256]

    int tid = threadIdx.x;
    int c = blockIdx.x;
    int gl = tid & 15, s = tid >> 4;
    int k0 = s * 32;

    const float* h_in  = g_h[t & 1];
    const float* c_in  = g_c[t & 1];
    float* h_out = g_h[(t + 1) & 1];
    float* c_out = g_c[(t + 1) & 1];

    float wreg[32];
    {
        const float* Wp = g_W3d + ((size_t)c*1024 + k0)*16 + gl;
        #pragma unroll
        for (int kk = 0; kk < 32; kk++) wreg[kk] = __ldg(Wp + kk*16);
    }

    #pragma unroll
    for (int b = 0; b < 16; b++)
        for (int k = tid; k < 1024; k += 512) {
            float v = (k < NH) ? g_attn[b*NH + k] : h_in[b*NH + (k - NH)];
            xs[k*PX + b] = v;
        }
    __syncthreads();

    u64 acc[8];
    #pragma unroll
    for (int p = 0; p < 8; p++) acc[p] = 0ULL;
    #pragma unroll
    for (int kk = 0; kk < 32; kk++) {
        u64 w2 = packdup(wreg[kk]);
        const u64* xk = (const u64*)(xs + (k0 + kk)*PX);
        #pragma unroll
        for (int p = 0; p < 8; p++) fma2(acc[p], xk[p], w2);
    }
    #pragma unroll
    for (int p = 0; p < 8; p++) {
        float lo, hi; unpack2(acc[p], lo, hi);
        zp[tid*PX + 2*p]   = lo;
        zp[tid*PX + 2*p+1] = hi;
    }
    __syncthreads();

    if (tid < 256) {
        int g2 = tid >> 4, b = tid & 15;
        float sum = g_Zxd[(((size_t)t*128 + c)*16 + g2)*16 + b]
                  + bias[(g2 & 3)*NH + (c << 2) + (g2 >> 2)];
        #pragma unroll
        for (int ss = 0; ss < 32; ss++) sum += zp[(g2 + 16*ss)*PX + b];
        zz[g2*16 + b] = sum;
    }
    __syncthreads();

    if (tid < 64) {
        int jl = tid >> 4, b = tid & 15;
        int jg = (c << 2) + jl;
        float iv = zz[(jl*4 + 0)*16 + b];
        float jv = zz[(jl*4 + 1)*16 + b];
        float fv = zz[(jl*4 + 2)*16 + b];
        float ov = zz[(jl*4 + 3)*16 + b];
        float cold = c_in[b*NH + jg];
        float c2 = cold * fsig(fv + 1.f) + fsig(iv) * ftanh(jv);
        float h2 = ftanh(c2) * fsig(ov);
        h_out[b*NH + jg] = h2;
        c_out[b*NH + jg] = c2;
    }
}

// ---------------- pq = h2 @ Wq : 128 CTAs x 256 thr ----------------
__global__ void __launch_bounds__(256, 1)
dec_pq(int t)
{
    extern __shared__ float sm[];
    float* zp = sm;   // [256*4]
    int tid = threadIdx.x;
    int c = blockIdx.x;
    int n0 = c * 4;
    int bq = tid & 15, ks = tid >> 4;
    const float* h2 = g_h[(t + 1) & 1];

    const float* hp = h2 + bq*NH + ks*32;
    const float4* wq4 = (const float4*)(g_Wq2 + (size_t)c*2048);
    float a0 = 0.f, a1 = 0.f, a2 = 0.f, a3 = 0.f;
    #pragma unroll
    for (int kk = 0; kk < 32; kk++) {
        float x = hp[kk];
        float4 w = __ldg(wq4 + ks*32 + kk);
        a0 = fmaf(x, w.x, a0);
        a1 = fmaf(x, w.y, a1);
        a2 = fmaf(x, w.z, a2);
        a3 = fmaf(x, w.w, a3);
    }
    zp[tid*4 + 0] = a0; zp[tid*4 + 1] = a1;
    zp[tid*4 + 2] = a2; zp[tid*4 + 3] = a3;
    __syncthreads();

    if (tid < 64) {
        int bb = tid >> 2, j = tid & 3;
        float sv = 0.f;
        #pragma unroll
        for (int ss = 0; ss < 16; ss++) sv += zp[(bb + 16*ss)*4 + j];
        g_pq[bb*NH + n0 + j] = sv;
    }
}

// ---------------- scores + softmax + ctx : 16 CTAs x 512 thr ----------------
__global__ void __launch_bounds__(512, 1)
dec_att(const float* __restrict__ vatt, const int* __restrict__ elen, int t)
{
    extern __shared__ float sm[];
    float* pqv = sm;          // [512]
    float* vsv = sm + 512;    // [512]
    float* scv = sm + 1024;   // [64]

    int tid = threadIdx.x;
    int b = blockIdx.x;

    pqv[tid] = g_pq[b*NH + tid];
    vsv[tid] = vatt[tid];
    __syncthreads();

    int w = tid >> 5, l = tid & 31;
    int len = elen[b];
    #pragma unroll
    for (int r = 0; r < 4; r++) {
        int te = w*4 + r;
        const float* kp = g_keys + ((size_t)b*NTE + te)*NH;
        float p = 0.f;
        #pragma unroll
        for (int j = 0; j < 16; j++) {
            int h = l + 32*j;
            p += vsv[h] * ftanh(kp[h] + pqv[h]);
        }
        #pragma unroll
        for (int off = 16; off > 0; off >>= 1) p += __shfl_xor_sync(0xffffffffu, p, off);
        if (l == 0) scv[te] = (te < len) ? p : NEGV;
    }
    __syncthreads();

    if (tid < 32) {
        float a = scv[tid], b2 = scv[tid + 32];
        float m = fmaxf(a, b2);
        #pragma unroll
        for (int off = 16; off > 0; off >>= 1) m = fmaxf(m, __shfl_xor_sync(0xffffffffu, m, off));
        float e1 = __expf(a - m), e2 = __expf(b2 - m);
        float ssum = e1 + e2;
        #pragma unroll
        for (int off = 16; off > 0; off >>= 1) ssum += __shfl_xor_sync(0xffffffffu, ssum, off);
        float inv = __fdividef(1.f, ssum);
        scv[tid] = e1 * inv; scv[tid + 32] = e2 * inv;
    }
    __syncthreads();

    {
        int h = tid;
        float acc = 0.f;
        const float* ep = g_encout + (size_t)b*NTE*NH + h;
        #pragma unroll 8
        for (int te = 0; te < NTE; te++)
            acc = fmaf(scv[te], ep[(size_t)te*NH], acc);
        g_ctx[b*NH + h] = acc;
    }
}

// ---------------- attn2 = [h2|ctx] @ Wa : 128 CTAs x 256 thr ----------------
__global__ void __launch_bounds__(256, 1)
dec_attn2(int t)
{
    extern __shared__ float sm[];
    float* zp = sm;
    int tid = threadIdx.x;
    int c = blockIdx.x;
    int n0 = c * 4;
    int bq = tid & 15, ks = tid >> 4;
    const float* h2 = g_h[(t + 1) & 1];

    const float* src = (ks < 8) ? (h2 + bq*NH + ks*64)
                                : (g_ctx + bq*NH + (ks - 8)*64);
    const float4* wa4 = (const float4*)(g_Wa2 + (size_t)c*4096);
    float a0 = 0.f, a1 = 0.f, a2 = 0.f, a3 = 0.f;
    #pragma unroll
    for (int kk = 0; kk < 64; kk++) {
        float x = src[kk];
        float4 w = __ldg(wa4 + ks*64 + kk);
        a0 = fmaf(x, w.x, a0);
        a1 = fmaf(x, w.y, a1);
        a2 = fmaf(x, w.z, a2);
        a3 = fmaf(x, w.w, a3);
    }
    zp[tid*4 + 0] = a0; zp[tid*4 + 1] = a1;
    zp[tid*4 + 2] = a2; zp[tid*4 + 3] = a3;
    __syncthreads();

    if (tid < 64) {
        int bb = tid >> 2, j = tid & 3;
        float sv = 0.f;
        #pragma unroll
        for (int ss = 0; ss < 16; ss++) sv += zp[(bb + 16*ss)*4 + j];
        g_attn[bb*NH + n0 + j] = sv;
        int m = g_rowpos[bb*NTD + t];
        if (m >= 0) {
            __nv_bfloat16 hi = __float2bfloat16(sv);
            g_Ahi[m*NH + n0 + j] = hi;
            g_Alo[m*NH + n0 + j] = __float2bfloat16(sv - __bfloat162float(hi));
        }
    }
}

// ---------------- HMMA projection (r10-proven) ----------------
#define PR_LDA 72
#define PROJ_SMEM (4*128*PR_LDA*2)

__device__ __forceinline__ void ldmA(uint32_t* a, uint32_t addr) {
    asm volatile("ldmatrix.sync.aligned.m8n8.x4.shared.b16 {%0,%1,%2,%3}, [%4];"
                 : "=r"(a[0]), "=r"(a[1]), "=r"(a[2]), "=r"(a[3]) : "r"(addr));
}
__device__ __forceinline__ void ldmB(uint32_t* b, uint32_t addr) {
    asm volatile("ldmatrix.sync.aligned.m8n8.x2.shared.b16 {%0,%1}, [%2];"
                 : "=r"(b[0]), "=r"(b[1]) : "r"(addr));
}
__device__ __forceinline__ void mma16816(float* c, const uint32_t* a, const uint32_t* b) {
    asm volatile("mma.sync.aligned.m16n8k16.row.col.f32.bf16.bf16.f32 "
                 "{%0,%1,%2,%3}, {%4,%5,%6,%7}, {%8,%9}, {%0,%1,%2,%3};"
                 : "+f"(c[0]), "+f"(c[1]), "+f"(c[2]), "+f"(c[3])
                 : "r"(a[0]), "r"(a[1]), "r"(a[2]), "r"(a[3]), "r"(b[0]), "r"(b[1]));
}

__global__ void __launch_bounds__(256, 1)
proj_hmma(const float* __restrict__ Wp, float* __restrict__ out)
{
    extern __shared__ __nv_bfloat16 smb[];
    __nv_bfloat16* sAhi = smb;
    __nv_bfloat16* sAlo = smb + 128*PR_LDA;
    __nv_bfloat16* sBhi = smb + 2*128*PR_LDA;
    __nv_bfloat16* sBlo = smb + 3*128*PR_LDA;

    int m0 = blockIdx.x * 128;
    int n0 = blockIdx.y * 128;
    int nr = g_nrows;
    if (m0 >= nr) return;

    int tid = threadIdx.x;
    int wid = tid >> 5, lane = tid & 31;
    int m0w = (wid >> 2) * 64;
    int n0w = (wid & 3) * 32;

    uint32_t sb = smem_u32(smb);
    uint32_t aAhi = sb, aAlo = sb + 128*PR_LDA*2, aBhi = sb + 2*128*PR_LDA*2, aBlo = sb + 3*128*PR_LDA*2;

    float c[4][4][4];
    #pragma unroll
    for (int i = 0; i < 4; i++)
        #pragma unroll
        for (int j = 0; j < 4; j++)
            #pragma unroll
            for (int q = 0; q < 4; q++) c[i][j][q] = 0.f;

    for (int ch = 0; ch < 8; ch++) {
        int k0 = ch * 64;
        for (int i = tid; i < 1024; i += 256) {
            int m = i >> 3, kb = i & 7;
            size_t go = (size_t)(m0 + m)*NH + k0 + kb*8;
            int so = m*PR_LDA + kb*8;
            *(uint4*)&sAhi[so] = *(const uint4*)&g_Ahi[go];
            *(uint4*)&sAlo[so] = *(const uint4*)&g_Alo[go];
        }
        for (int i = tid; i < 4096; i += 256) {
            int n = i & 127, kkp = i >> 7;
            int kk = kkp * 2;
            int nn = n0 + n;
            float w0 = 0.f, w1 = 0.f;
            if (nn < NV) {
                w0 = Wp[(size_t)(k0 + kk)*NV + nn];
                w1 = Wp[(size_t)(k0 + kk + 1)*NV + nn];
            }
            __nv_bfloat16 h0 = __float2bfloat16(w0);
            __nv_bfloat16 h1 = __float2bfloat16(w1);
            float r0 = w0 - __bfloat162float(h0);
            float r1 = w1 - __bfloat162float(h1);
            __nv_bfloat16 l0 = __float2bfloat16(r0);
            __nv_bfloat16 l1 = __float2bfloat16(r1);
            uint32_t hv = (uint32_t)__bfloat16_as_ushort(h0) |
                          ((uint32_t)__bfloat16_as_ushort(h1) << 16);
            uint32_t lv = (uint32_t)__bfloat16_as_ushort(l0) |
                          ((uint32_t)__bfloat16_as_ushort(l1) << 16);
            int so = n*PR_LDA + kk;
            *(uint32_t*)&sBhi[so] = hv;
            *(uint32_t*)&sBlo[so] = lv;
        }
        __syncthreads();

        #pragma unroll
        for (int ksp = 0; ksp < 4; ksp++) {
            int kp = ksp * 16;
            uint32_t ahi[4][4], alo[4][4], bhi[4][2], blo[4][2];
            #pragma unroll
            for (int mt = 0; mt < 4; mt++) {
                uint32_t off = ((m0w + mt*16 + (lane & 15)) * PR_LDA + kp + ((lane >> 4) << 3)) * 2;
                ldmA(ahi[mt], aAhi + off);
                ldmA(alo[mt], aAlo + off);
            }
            #pragma unroll
            for (int nt = 0; nt < 4; nt++) {
                uint32_t off = ((n0w + nt*8 + (lane & 7)) * PR_LDA + kp + (((lane >> 3) & 1) << 3)) * 2;
                ldmB(bhi[nt], aBhi + off);
                ldmB(blo[nt], aBlo + off);
            }
            #pragma unroll
            for (int mt = 0; mt < 4; mt++)
                #pragma unroll
                for (int nt = 0; nt < 4; nt++) {
                    mma16816(c[mt][nt], ahi[mt], bhi[nt]);
                    mma16816(c[mt][nt], ahi[mt], blo[nt]);
                    mma16816(c[mt][nt], alo[mt], bhi[nt]);
                }
        }
        __syncthreads();
    }

    int rg = lane >> 2, cg = (lane & 3) * 2;
    #pragma unroll
    for (int mt = 0; mt < 4; mt++) {
        #pragma unroll
        for (int half = 0; half < 2; half++) {
            int mloc = m0w + mt*16 + rg + half*8;
            int m = m0 + mloc;
            if (m < nr) {
                int orow = g_outrow[m];
                float* obase = out + (size_t)orow*NV;
                #pragma unroll
                for (int nt = 0; nt < 4; nt++) {
                    int nn = n0 + n0w + nt*8 + cg;
                    float v0 = c[mt][nt][half*2 + 0];
                    float v1 = c[mt][nt][half*2 + 1];
                    if (nn + 1 < NV) {
                        *(float2*)(obase + nn) = make_float2(v0, v1);
                    } else if (nn < NV) {
                        obase[nn] = v0;
                    }
                }
            }
        }
    }
}

// ---------------- launch ----------------
extern "C" void kernel_launch(void* const* d_in, const int* in_sizes, int n_in,
                              void* d_out, int out_size)
{
    const int*   enc_in  = (const int*)d_in[0];
    const int*   dec_in  = (const int*)d_in[1];
    const int*   elen    = (const int*)d_in[2];
    const int*   dlen    = (const int*)d_in[3];
    const float* emb     = (const float*)d_in[4];
    const float* W_enc   = (const float*)d_in[5];
    const float* b_enc   = (const float*)d_in[6];
    const float* W_dec   = (const float*)d_in[7];
    const float* b_dec   = (const float*)d_in[8];
    const float* W_mem   = (const float*)d_in[9];
    const float* W_query = (const float*)d_in[10];
    const float* v_att   = (const float*)d_in[11];
    const float* W_attn  = (const float*)d_in[12];
    const float* W_proj  = (const float*)d_in[13];
    float* out = (float*)d_out;

    // uniform dynamic smem across ALL recurrent-loop kernels: no carveout reconfig
    const int SMEM_UNI = (1024*PX + 512*PX + 256) * 4;   // 111,616 B

    cudaFuncSetAttribute(zx_kernel,   cudaFuncAttributeMaxDynamicSharedMemorySize, SMEM_UNI);
    cudaFuncSetAttribute(enc_step,    cudaFuncAttributeMaxDynamicSharedMemorySize, SMEM_UNI);
    cudaFuncSetAttribute(dec_lstm,    cudaFuncAttributeMaxDynamicSharedMemorySize, SMEM_UNI);
    cudaFuncSetAttribute(dec_pq,      cudaFuncAttributeMaxDynamicSharedMemorySize, SMEM_UNI);
    cudaFuncSetAttribute(dec_att,     cudaFuncAttributeMaxDynamicSharedMemorySize, SMEM_UNI);
    cudaFuncSetAttribute(dec_attn2,   cudaFuncAttributeMaxDynamicSharedMemorySize, SMEM_UNI);
    cudaFuncSetAttribute(keys_kernel, cudaFuncAttributeMaxDynamicSharedMemorySize, SMEM_UNI);
    cudaFuncSetAttribute(proj_hmma,   cudaFuncAttributeMaxDynamicSharedMemorySize, PROJ_SMEM);
    // pin carveout to max-shared for everything so the SM config never changes
    cudaFuncSetAttribute(prep_kernel, cudaFuncAttributePreferredSharedMemoryCarveout, 100);
    cudaFuncSetAttribute(permW_kernel,cudaFuncAttributePreferredSharedMemoryCarveout, 100);
    cudaFuncSetAttribute(zero_kernel, cudaFuncAttributePreferredSharedMemoryCarveout, 100);
    cudaFuncSetAttribute(zx_kernel,   cudaFuncAttributePreferredSharedMemoryCarveout, 100);
    cudaFuncSetAttribute(enc_step,    cudaFuncAttributePreferredSharedMemoryCarveout, 100);
    cudaFuncSetAttribute(dec_lstm,    cudaFuncAttributePreferredSharedMemoryCarveout, 100);
    cudaFuncSetAttribute(dec_pq,      cudaFuncAttributePreferredSharedMemoryCarveout, 100);
    cudaFuncSetAttribute(dec_att,     cudaFuncAttributePreferredSharedMemoryCarveout, 100);
    cudaFuncSetAttribute(dec_attn2,   cudaFuncAttributePreferredSharedMemoryCarveout, 100);
    cudaFuncSetAttribute(keys_kernel, cudaFuncAttributePreferredSharedMemoryCarveout, 100);
    cudaFuncSetAttribute(proj_hmma,   cudaFuncAttributePreferredSharedMemoryCarveout, 100);

    prep_kernel<<<256, 256>>>(enc_in, dec_in, dlen, emb);
    permW_kernel<<<1024, 256>>>(W_enc, W_dec, W_query, W_attn);
    zero_kernel<<<dim3(88, 512), 256>>>((float4*)out);
    zx_kernel<<<dim3(128, NTE/8), 256, SMEM_UNI>>>(0);
    zx_kernel<<<dim3(128, NTD/8), 256, SMEM_UNI>>>(1);

    for (int t = 0; t < NTE; t++)
        enc_step<<<128, 512, SMEM_UNI>>>(b_enc, elen, t);

    keys_kernel<<<dim3(32, 64), 256, SMEM_UNI>>>(W_mem);

    for (int t = 0; t < NTD; t++) {
        dec_lstm<<<128, 512, SMEM_UNI>>>(b_dec, t);
        dec_pq<<<128, 256, SMEM_UNI>>>(t);
        dec_att<<<16, 512, SMEM_UNI>>>(v_att, elen, t);
        dec_attn2<<<128, 256, SMEM_UNI>>>(t);
    }

    proj_hmma<<<dim3(4, 704), 256, PROJ_SMEM>>>(W_proj, out);
}